// round 3
// baseline (speedup 1.0000x reference)
#include <cuda_runtime.h>

#define NP 8192
#define NQ (2*NP)

__device__ __align__(16) float g_U[NQ*128];
__device__ float g_cd[NQ*128];
__device__ int   g_ci[NQ*128];
__device__ int   g_knn[NQ*16];
__device__ __align__(16) float g_wu [64*128];  // [c][o]: o<64 -> Wn, else We
__device__ __align__(16) float g_w1t[64*64];   // [c][o]
__device__ __align__(16) float g_w2t[64*128];  // [c][o]

__device__ __forceinline__ float leaky(float v){ return fmaxf(v, 0.2f*v); }

// ---------------- prep: transpose weights once ----------------
__global__ void prep_kernel(const float* __restrict__ Wn, const float* __restrict__ We,
                            const float* __restrict__ W1, const float* __restrict__ W2){
    int i = blockIdx.x*blockDim.x + threadIdx.x;   // 0..20479
    if (i < 8192){
        int c = i >> 7, o = i & 127;
        g_wu[i] = (o < 64) ? Wn[o*64 + c] : We[(o-64)*64 + c];
    } else if (i < 12288){
        int j = i - 8192; int c = j >> 6, o = j & 63;
        g_w1t[j] = W1[o*64 + c];
    } else if (i < 20480){
        int j = i - 12288; int c = j >> 7, o = j & 127;
        g_w2t[j] = W2[o*64 + c];
    }
}

// ---------------- KNN: 8 segments/query, per-thread top-16 over 1024 ----------------
__global__ void knn_kernel(const float* __restrict__ pos){
    __shared__ float4 tile[256];
    int blk  = blockIdx.x;
    int b    = blk >> 8;
    int rem  = blk & 255;
    int seg  = rem >> 5;
    int n    = ((rem & 31) << 8) + threadIdx.x;
    const float* pb = pos + b*NP*3;
    float xi = pb[n*3+0], yi = pb[n*3+1], zi = pb[n*3+2];

    float bd[16]; int bi[16];
#pragma unroll
    for (int s=0;s<16;s++){ bd[s]=3.4e38f; bi[s]=0; }
    float worst = 3.4e38f; int wslot = 0;

    const int base0 = seg*1024;
    for (int t=0;t<4;t++){
        int j = base0 + (t<<8) + threadIdx.x;
        float x = pb[j*3+0], y = pb[j*3+1], z = pb[j*3+2];
        float sq = x*x; sq = fmaf(y,y,sq); sq = fmaf(z,z,sq);
        __syncthreads();
        tile[threadIdx.x] = make_float4(-2.0f*x, -2.0f*y, -2.0f*z, sq);
        __syncthreads();
        int jb = base0 + (t<<8);
        for (int jj=0;jj<256;jj+=4){
            float4 c0=tile[jj+0], c1=tile[jj+1], c2=tile[jj+2], c3=tile[jj+3];
            float d0 = fmaf(zi,c0.z,fmaf(yi,c0.y,fmaf(xi,c0.x,c0.w)));
            float d1 = fmaf(zi,c1.z,fmaf(yi,c1.y,fmaf(xi,c1.x,c1.w)));
            float d2 = fmaf(zi,c2.z,fmaf(yi,c2.y,fmaf(xi,c2.x,c2.w)));
            float d3 = fmaf(zi,c3.z,fmaf(yi,c3.y,fmaf(xi,c3.x,c3.w)));
            float mn = fminf(fminf(d0,d1),fminf(d2,d3));
            if (mn < worst){
                float dd[4] = {d0,d1,d2,d3};
#pragma unroll
                for (int u=0;u<4;u++){
                    if (dd[u] < worst){
                        int id = jb + jj + u;
#pragma unroll
                        for (int s=0;s<16;s++) if (s==wslot){ bd[s]=dd[u]; bi[s]=id; }
                        worst = bd[0]; wslot = 0;
#pragma unroll
                        for (int s=1;s<16;s++) if (bd[s]>worst){ worst=bd[s]; wslot=s; }
                    }
                }
            }
        }
    }
    long base = ((long)(b*NP + n))*128 + (long)seg*16;
#pragma unroll
    for (int s=0;s<16;s++){ g_cd[base+s]=bd[s]; g_ci[base+s]=bi[s]; }
}

// ---------------- merge: warp per query, 16 rounds of lexicographic min ----------------
__global__ void knn_merge(){
    int warp = (blockIdx.x*blockDim.x + threadIdx.x) >> 5;  // 0..16383
    int lane = threadIdx.x & 31;
    long base = (long)warp*128 + lane*4;
    float d[4]; int ix[4];
#pragma unroll
    for (int u=0;u<4;u++){ d[u]=g_cd[base+u]; ix[u]=g_ci[base+u]; }

    for (int r=0;r<16;r++){
        float ld = d[0]; int li = ix[0];
#pragma unroll
        for (int u=1;u<4;u++){
            bool better = (d[u] < ld) || (d[u]==ld && ix[u] < li);
            ld = better ? d[u] : ld;
            li = better ? ix[u] : li;
        }
        float rd = ld; int ri = li;
#pragma unroll
        for (int o=16;o;o>>=1){
            float od = __shfl_down_sync(0xffffffff, rd, o);
            int   oi = __shfl_down_sync(0xffffffff, ri, o);
            bool better = (od < rd) || (od==rd && oi < ri);
            rd = better ? od : rd;
            ri = better ? oi : ri;
        }
        ri = __shfl_sync(0xffffffff, ri, 0);
        if (lane==0) g_knn[(long)warp*16 + r] = ri;
#pragma unroll
        for (int u=0;u<4;u++) if (ix[u]==ri) d[u] = 3.4e38f;
    }
}

// ---------------- U = [W_node; W_edge] * feat, per point ----------------
__global__ void u_kernel(const float* __restrict__ feat){
    extern __shared__ float smC[];
    float* fs = smC;            // [64][128]
    float* ws = smC + 64*128;   // [64][128]
    int q0 = blockIdx.x*128;
    int b  = q0 >> 13;
    int n0 = q0 & 8191;
    for (int i=threadIdx.x; i<64*128; i+=256){
        int c = i>>7, nn = i&127;
        fs[i] = feat[((long)(b*64 + c))*NP + n0 + nn];
        ws[i] = g_wu[i];
    }
    __syncthreads();
    int tx = threadIdx.x & 15, ty = threadIdx.x >> 4;
    float acc[8][8];
#pragma unroll
    for (int i=0;i<8;i++)
#pragma unroll
        for (int j=0;j<8;j++) acc[i][j]=0.f;
#pragma unroll 4
    for (int c=0;c<64;c++){
        float4 a0 = *(const float4*)&fs[c*128 + ty*8];
        float4 a1 = *(const float4*)&fs[c*128 + ty*8 + 4];
        float4 w0 = *(const float4*)&ws[c*128 + tx*8];
        float4 w1 = *(const float4*)&ws[c*128 + tx*8 + 4];
        float av[8] = {a0.x,a0.y,a0.z,a0.w,a1.x,a1.y,a1.z,a1.w};
        float bv[8] = {w0.x,w0.y,w0.z,w0.w,w1.x,w1.y,w1.z,w1.w};
#pragma unroll
        for (int i=0;i<8;i++)
#pragma unroll
            for (int j=0;j<8;j++) acc[i][j] = fmaf(av[i], bv[j], acc[i][j]);
    }
#pragma unroll
    for (int i=0;i<8;i++){
        long q = q0 + ty*8 + i;
        float* r = &g_U[q*128 + tx*8];
        *(float4*)r     = make_float4(acc[i][0],acc[i][1],acc[i][2],acc[i][3]);
        *(float4*)(r+4) = make_float4(acc[i][4],acc[i][5],acc[i][6],acc[i][7]);
    }
}

// ---------------- fused gather + h1 + m1 + m2 + maxpool ----------------
__global__ void edge_main(const float* __restrict__ bn,  const float* __restrict__ be,
                          const float* __restrict__ vb1, const float* __restrict__ vb2,
                          float* __restrict__ out){
    extern __shared__ float sm[];
    float* h1T = sm;                  // [64][136]
    float* h2T = h1T + 64*136;        // [64][136]
    float* w1s = h2T + 64*136;        // [c][o] 64x64
    float* w2s = w1s + 64*64;         // [c][o] 64x128
    float* uec = w2s + 64*128;        // [8][64]
    float* red = uec + 512;           // [16][128]
    float* bns = red + 2048;
    float* bes = bns + 64;
    float* b1s = bes + 64;
    float* b2s = b1s + 64;            // 128
    int*   idxs = (int*)(b2s + 128);  // 128

    int q0 = blockIdx.x*8;
    int b  = q0 >> 13;
    int n0 = q0 & 8191;
    int tid = threadIdx.x;

    // conflict-free linear copies from pre-transposed scratch
    for (int i=tid;i<4096;i+=256) w1s[i] = g_w1t[i];
    for (int i=tid;i<8192;i+=256) w2s[i] = g_w2t[i];
    if (tid<64){ bns[tid]=bn[tid]; bes[tid]=be[tid]; b1s[tid]=vb1[tid]; }
    if (tid<128) b2s[tid]=vb2[tid];
    if (tid<128) idxs[tid] = g_knn[(long)q0*16 + tid];
    for (int i=tid;i<512;i+=256){ int p=i>>6, j=i&63; uec[i] = g_U[(long)(q0+p)*128 + 64 + j]; }
    __syncthreads();

    { // stage A: gather + layer1, store h1T[j][m]
        int m  = tid >> 1;
        int jb = (tid & 1) * 32;
        int p  = m >> 4;
        int nb = idxs[m];
        const float* Ur = &g_U[(long)((b<<13) + nb)*128];
#pragma unroll
        for (int v=0; v<8; v++){
            float4 un = *(const float4*)&Ur[jb + v*4];
            float4 ue = *(const float4*)&Ur[64 + jb + v*4];
            float unv[4] = {un.x,un.y,un.z,un.w};
            float uev[4] = {ue.x,ue.y,ue.z,ue.w};
#pragma unroll
            for (int e=0;e<4;e++){
                int j = jb + v*4 + e;
                float a = leaky(unv[e] + bns[j]);
                float c = leaky(uev[e] - uec[p*64 + j] + bes[j]);
                h1T[j*136 + m] = a + c;
            }
        }
    }
    __syncthreads();

    int tx = tid & 15, ty = tid >> 4;

    { // stage B: M=128 N=64 K=64
        float acc[8][4];
#pragma unroll
        for (int i=0;i<8;i++)
#pragma unroll
            for (int o=0;o<4;o++) acc[i][o]=0.f;
#pragma unroll 4
        for (int c=0;c<64;c++){
            float4 a0 = *(const float4*)&h1T[c*136 + ty*8];
            float4 a1 = *(const float4*)&h1T[c*136 + ty*8 + 4];
            float4 wv = *(const float4*)&w1s[c*64 + tx*4];
            float av[8] = {a0.x,a0.y,a0.z,a0.w,a1.x,a1.y,a1.z,a1.w};
            float bb[4] = {wv.x,wv.y,wv.z,wv.w};
#pragma unroll
            for (int i=0;i<8;i++)
#pragma unroll
                for (int o=0;o<4;o++) acc[i][o] = fmaf(av[i], bb[o], acc[i][o]);
        }
#pragma unroll
        for (int i=0;i<8;i++){
            int m = ty*8 + i;
#pragma unroll
            for (int o=0;o<4;o++)
                h2T[(tx*4+o)*136 + m] = leaky(acc[i][o] + b1s[tx*4+o]);
        }
    }
    __syncthreads();

    { // stage C: M=128 N=128 K=64 + partial max over 8 rows
        float acc[8][8];
#pragma unroll
        for (int i=0;i<8;i++)
#pragma unroll
            for (int o=0;o<8;o++) acc[i][o]=0.f;
#pragma unroll 4
        for (int c=0;c<64;c++){
            float4 a0 = *(const float4*)&h2T[c*136 + ty*8];
            float4 a1 = *(const float4*)&h2T[c*136 + ty*8 + 4];
            float4 w0 = *(const float4*)&w2s[c*128 + tx*8];
            float4 w1 = *(const float4*)&w2s[c*128 + tx*8 + 4];
            float av[8] = {a0.x,a0.y,a0.z,a0.w,a1.x,a1.y,a1.z,a1.w};
            float bb[8] = {w0.x,w0.y,w0.z,w0.w,w1.x,w1.y,w1.z,w1.w};
#pragma unroll
            for (int i=0;i<8;i++)
#pragma unroll
                for (int o=0;o<8;o++) acc[i][o] = fmaf(av[i], bb[o], acc[i][o]);
        }
#pragma unroll
        for (int o=0;o<8;o++){
            float bias = b2s[tx*8+o];
            float pm = -3.4e38f;
#pragma unroll
            for (int i=0;i<8;i++)
                pm = fmaxf(pm, leaky(acc[i][o] + bias));
            red[ty*128 + tx*8 + o] = pm;
        }
    }
    __syncthreads();

    for (int e=tid; e<1024; e+=256){
        int o = e & 127;
        int p = e >> 7;
        float v = fmaxf(red[(2*p)*128 + o], red[(2*p+1)*128 + o]);
        out[((long)(b*128 + o))*NP + n0 + p] = v;
    }
}

extern "C" void kernel_launch(void* const* d_in, const int* in_sizes, int n_in,
                              void* d_out, int out_size){
    const float* feat = (const float*)d_in[0];
    const float* pos  = (const float*)d_in[1];
    const float* Wn   = (const float*)d_in[2];
    const float* bn   = (const float*)d_in[3];
    const float* We   = (const float*)d_in[4];
    const float* be   = (const float*)d_in[5];
    const float* W1   = (const float*)d_in[6];
    const float* b1   = (const float*)d_in[7];
    const float* W2   = (const float*)d_in[8];
    const float* b2   = (const float*)d_in[9];
    float* out = (float*)d_out;

    cudaFuncSetAttribute(u_kernel,  cudaFuncAttributeMaxDynamicSharedMemorySize, 65536);
    cudaFuncSetAttribute(edge_main, cudaFuncAttributeMaxDynamicSharedMemorySize, 131072);

    prep_kernel<<<80,256>>>(Wn, We, W1, W2);
    knn_kernel<<<512,256>>>(pos);
    knn_merge<<<2048,256>>>();
    u_kernel<<<128,256,65536>>>(feat);
    edge_main<<<2048,256,130816>>>(bn, be, b1, b2, out);
}

// round 4
// speedup vs baseline: 1.9868x; 1.9868x over previous
#include <cuda_runtime.h>

#define NP 8192
#define NQ (2*NP)

__device__ __align__(16) float g_U[NQ*128];
__device__ float g_cmin[NQ*16];                         // 16 chunk-mins per query
__device__ unsigned long long g_surv[(long)NQ*4*128];   // survivor keys
__device__ int   g_scnt[NQ*4];
__device__ int   g_knn[NQ*16];
__device__ __align__(16) float g_wu [64*128];
__device__ __align__(16) float g_w1t[64*64];
__device__ __align__(16) float g_w2t[64*128];

__device__ __forceinline__ float leaky(float v){ return fmaxf(v, 0.2f*v); }

__device__ __forceinline__ float distp(float xi,float yi,float zi,const float4 c){
    return fmaf(zi,c.z,fmaf(yi,c.y,fmaf(xi,c.x,c.w)));
}
__device__ __forceinline__ unsigned int okey(float d){
    unsigned int u = __float_as_uint(d);
    u ^= ((unsigned int)((int)u >> 31)) | 0x80000000u;
    return u;
}

// ---------------- prep: transpose weights once ----------------
__global__ void prep_kernel(const float* __restrict__ Wn, const float* __restrict__ We,
                            const float* __restrict__ W1, const float* __restrict__ W2){
    int i = blockIdx.x*blockDim.x + threadIdx.x;
    if (i < 8192){
        int c = i >> 7, o = i & 127;
        g_wu[i] = (o < 64) ? Wn[o*64 + c] : We[(o-64)*64 + c];
    } else if (i < 12288){
        int j = i - 8192; int c = j >> 6, o = j & 63;
        g_w1t[j] = W1[o*64 + c];
    } else if (i < 20480){
        int j = i - 12288; int c = j >> 7, o = j & 127;
        g_w2t[j] = W2[o*64 + c];
    }
}

// ---------------- KNN pass 1: branchless chunk-mins (8 chunks of 512 per half) ---------
__global__ void knn_pass1(const float* __restrict__ pos){
    __shared__ float4 tile[128];
    int bx   = blockIdx.x;            // 256 blocks
    int b    = bx >> 7;
    int r    = bx & 127;
    int half = r & 1;
    int n    = (r >> 1)*128 + threadIdx.x;
    const float* pb = pos + b*NP*3;
    float xi = pb[n*3+0], yi = pb[n*3+1], zi = pb[n*3+2];
    long obase = ((long)(b*NP + n))*16 + half*8;

#pragma unroll
    for (int c8 = 0; c8 < 8; c8++){
        int cbase = half*4096 + c8*512;
        float mA = 3.4e38f, mB = 3.4e38f;
#pragma unroll
        for (int t = 0; t < 4; t++){
            int j = cbase + t*128 + threadIdx.x;
            float x = pb[j*3+0], y = pb[j*3+1], z = pb[j*3+2];
            float sq = x*x; sq = fmaf(y,y,sq); sq = fmaf(z,z,sq);
            __syncthreads();
            tile[threadIdx.x] = make_float4(-2.0f*x, -2.0f*y, -2.0f*z, sq);
            __syncthreads();
#pragma unroll 8
            for (int jj = 0; jj < 128; jj += 4){
                float d0 = distp(xi,yi,zi, tile[jj+0]);
                float d1 = distp(xi,yi,zi, tile[jj+1]);
                float d2 = distp(xi,yi,zi, tile[jj+2]);
                float d3 = distp(xi,yi,zi, tile[jj+3]);
                mA = fminf(mA, fminf(d0,d1));
                mB = fminf(mB, fminf(d2,d3));
            }
        }
        g_cmin[obase + c8] = fminf(mA, mB);
    }
}

// ---------------- KNN pass 2: filtered survivor scan (4 segs of 2048) ----------------
__global__ void knn_pass2(const float* __restrict__ pos){
    __shared__ float4 tile[256];
    int bx  = blockIdx.x;             // 256 blocks
    int seg = bx & 3;
    int q   = (bx >> 2)*256 + threadIdx.x;   // 0..16383
    int b   = q >> 13;
    int n   = q & 8191;
    const float* pb = pos + b*NP*3;
    float xi = pb[n*3+0], yi = pb[n*3+1], zi = pb[n*3+2];

    float T0 = -3.4e38f;
#pragma unroll
    for (int s = 0; s < 16; s++) T0 = fmaxf(T0, g_cmin[(long)q*16 + s]);

    unsigned long long* sv = &g_surv[((long)q*4 + seg)*128];
    int c = 0;
    for (int t = 0; t < 8; t++){
        int jb = seg*2048 + t*256;
        int j  = jb + threadIdx.x;
        float x = pb[j*3+0], y = pb[j*3+1], z = pb[j*3+2];
        float sq = x*x; sq = fmaf(y,y,sq); sq = fmaf(z,z,sq);
        __syncthreads();
        tile[threadIdx.x] = make_float4(-2.0f*x, -2.0f*y, -2.0f*z, sq);
        __syncthreads();
        for (int jj = 0; jj < 256; jj += 4){
            float d0 = distp(xi,yi,zi, tile[jj+0]);
            float d1 = distp(xi,yi,zi, tile[jj+1]);
            float d2 = distp(xi,yi,zi, tile[jj+2]);
            float d3 = distp(xi,yi,zi, tile[jj+3]);
            float mn = fminf(fminf(d0,d1), fminf(d2,d3));
            if (mn <= T0){
                float dd[4] = {d0,d1,d2,d3};
#pragma unroll
                for (int u = 0; u < 4; u++){
                    if (dd[u] <= T0 && c < 128){
                        sv[c] = ((unsigned long long)okey(dd[u]) << 32) | (unsigned int)(jb + jj + u);
                        c++;
                    }
                }
            }
        }
    }
    g_scnt[(long)q*4 + seg] = c;
}

// ---------------- KNN pass 3: exact top-16 among survivors ----------------
__global__ void knn_pass3(const float* __restrict__ pos){
    int q = blockIdx.x*blockDim.x + threadIdx.x;   // 16384
    int b = q >> 13;
    int n = q & 8191;
    int cnt[4]; bool ovf = false;
#pragma unroll
    for (int s = 0; s < 4; s++){
        cnt[s] = g_scnt[(long)q*4 + s];
        if (cnt[s] >= 128) ovf = true;
    }
    if (!ovf){
        unsigned long long buf[512];
        int c = 0;
        for (int s = 0; s < 4; s++){
            const unsigned long long* sv = &g_surv[((long)q*4 + s)*128];
            for (int i = 0; i < cnt[s]; i++) buf[c++] = sv[i];
        }
        for (int rr = 0; rr < 16; rr++){
            unsigned long long best = ~0ull; int bj = 0;
            for (int i = 0; i < c; i++)
                if (buf[i] < best){ best = buf[i]; bj = i; }
            buf[bj] = ~0ull;
            g_knn[(long)q*16 + rr] = (int)(best & 0xffffffffull);
        }
    } else {
        // exact full rescan (rare fallback)
        const float* pb = pos + b*NP*3;
        float xi = pb[n*3+0], yi = pb[n*3+1], zi = pb[n*3+2];
        unsigned long long bk[16];
#pragma unroll
        for (int s = 0; s < 16; s++) bk[s] = ~0ull;
        unsigned long long worst = ~0ull; int ws = 0;
        for (int j = 0; j < NP; j++){
            float x = pb[j*3+0], y = pb[j*3+1], z = pb[j*3+2];
            float sq = x*x; sq = fmaf(y,y,sq); sq = fmaf(z,z,sq);
            float d = fmaf(zi,-2.0f*z, fmaf(yi,-2.0f*y, fmaf(xi,-2.0f*x, sq)));
            unsigned long long key = ((unsigned long long)okey(d) << 32) | (unsigned int)j;
            if (key < worst){
                bk[ws] = key;
                worst = bk[0]; ws = 0;
                for (int s = 1; s < 16; s++) if (bk[s] > worst){ worst = bk[s]; ws = s; }
            }
        }
        for (int rr = 0; rr < 16; rr++){
            unsigned long long best = ~0ull; int bj = 0;
            for (int s = 0; s < 16; s++) if (bk[s] < best){ best = bk[s]; bj = s; }
            bk[bj] = ~0ull;
            g_knn[(long)q*16 + rr] = (int)(best & 0xffffffffull);
        }
    }
}

// ---------------- U = [W_node; W_edge] * feat ----------------
__global__ void u_kernel(const float* __restrict__ feat){
    extern __shared__ float smC[];
    float* fs = smC;
    float* ws = smC + 64*128;
    int q0 = blockIdx.x*128;
    int b  = q0 >> 13;
    int n0 = q0 & 8191;
    for (int i=threadIdx.x; i<64*128; i+=256){
        int c = i>>7, nn = i&127;
        fs[i] = feat[((long)(b*64 + c))*NP + n0 + nn];
        ws[i] = g_wu[i];
    }
    __syncthreads();
    int tx = threadIdx.x & 15, ty = threadIdx.x >> 4;
    float acc[8][8];
#pragma unroll
    for (int i=0;i<8;i++)
#pragma unroll
        for (int j=0;j<8;j++) acc[i][j]=0.f;
#pragma unroll 4
    for (int c=0;c<64;c++){
        float4 a0 = *(const float4*)&fs[c*128 + ty*8];
        float4 a1 = *(const float4*)&fs[c*128 + ty*8 + 4];
        float4 w0 = *(const float4*)&ws[c*128 + tx*8];
        float4 w1 = *(const float4*)&ws[c*128 + tx*8 + 4];
        float av[8] = {a0.x,a0.y,a0.z,a0.w,a1.x,a1.y,a1.z,a1.w};
        float bv[8] = {w0.x,w0.y,w0.z,w0.w,w1.x,w1.y,w1.z,w1.w};
#pragma unroll
        for (int i=0;i<8;i++)
#pragma unroll
            for (int j=0;j<8;j++) acc[i][j] = fmaf(av[i], bv[j], acc[i][j]);
    }
#pragma unroll
    for (int i=0;i<8;i++){
        long q = q0 + ty*8 + i;
        float* r = &g_U[q*128 + tx*8];
        *(float4*)r     = make_float4(acc[i][0],acc[i][1],acc[i][2],acc[i][3]);
        *(float4*)(r+4) = make_float4(acc[i][4],acc[i][5],acc[i][6],acc[i][7]);
    }
}

// ---------------- fused gather + h1 + m1 + m2 + maxpool (h2T reuses h1T) -------------
__global__ void edge_main(const float* __restrict__ bn,  const float* __restrict__ be,
                          const float* __restrict__ vb1, const float* __restrict__ vb2,
                          float* __restrict__ out){
    extern __shared__ float sm[];
    float* h1T = sm;                  // [64][136], reused as h2T
    float* w1s = h1T + 64*136;
    float* w2s = w1s + 64*64;
    float* uec = w2s + 64*128;        // [8][64]
    float* red = uec + 512;           // [16][128]
    float* bns = red + 2048;
    float* bes = bns + 64;
    float* b1s = bes + 64;
    float* b2s = b1s + 64;            // 128
    int*   idxs = (int*)(b2s + 128);  // 128

    int q0 = blockIdx.x*8;
    int b  = q0 >> 13;
    int n0 = q0 & 8191;
    int tid = threadIdx.x;

    for (int i=tid;i<4096;i+=256) w1s[i] = g_w1t[i];
    for (int i=tid;i<8192;i+=256) w2s[i] = g_w2t[i];
    if (tid<64){ bns[tid]=bn[tid]; bes[tid]=be[tid]; b1s[tid]=vb1[tid]; }
    if (tid<128) b2s[tid]=vb2[tid];
    if (tid<128) idxs[tid] = g_knn[(long)q0*16 + tid];
    for (int i=tid;i<512;i+=256){ int p=i>>6, j=i&63; uec[i] = g_U[(long)(q0+p)*128 + 64 + j]; }
    __syncthreads();

    { // stage A: gather + layer1 -> h1T[j][m]
        int m  = tid >> 1;
        int jb = (tid & 1) * 32;
        int p  = m >> 4;
        int nb = idxs[m];
        const float* Ur = &g_U[(long)((b<<13) + nb)*128];
#pragma unroll
        for (int v=0; v<8; v++){
            float4 un = *(const float4*)&Ur[jb + v*4];
            float4 ue = *(const float4*)&Ur[64 + jb + v*4];
            float unv[4] = {un.x,un.y,un.z,un.w};
            float uev[4] = {ue.x,ue.y,ue.z,ue.w};
#pragma unroll
            for (int e=0;e<4;e++){
                int j = jb + v*4 + e;
                float a = leaky(unv[e] + bns[j]);
                float c = leaky(uev[e] - uec[p*64 + j] + bes[j]);
                h1T[j*136 + m] = a + c;
            }
        }
    }
    __syncthreads();

    int tx = tid & 15, ty = tid >> 4;

    { // stage B: M=128 N=64 K=64 ; results held in regs, then h1T overwritten as h2T
        float acc[8][4];
#pragma unroll
        for (int i=0;i<8;i++)
#pragma unroll
            for (int o=0;o<4;o++) acc[i][o]=0.f;
#pragma unroll 4
        for (int c=0;c<64;c++){
            float4 a0 = *(const float4*)&h1T[c*136 + ty*8];
            float4 a1 = *(const float4*)&h1T[c*136 + ty*8 + 4];
            float4 wv = *(const float4*)&w1s[c*64 + tx*4];
            float av[8] = {a0.x,a0.y,a0.z,a0.w,a1.x,a1.y,a1.z,a1.w};
            float bb[4] = {wv.x,wv.y,wv.z,wv.w};
#pragma unroll
            for (int i=0;i<8;i++)
#pragma unroll
                for (int o=0;o<4;o++) acc[i][o] = fmaf(av[i], bb[o], acc[i][o]);
        }
        __syncthreads();   // all h1T reads complete before overwrite
#pragma unroll
        for (int i=0;i<8;i++){
            int m = ty*8 + i;
#pragma unroll
            for (int o=0;o<4;o++)
                h1T[(tx*4+o)*136 + m] = leaky(acc[i][o] + b1s[tx*4+o]);
        }
    }
    __syncthreads();

    { // stage C: M=128 N=128 K=64 + partial max
        float acc[8][8];
#pragma unroll
        for (int i=0;i<8;i++)
#pragma unroll
            for (int o=0;o<8;o++) acc[i][o]=0.f;
#pragma unroll 4
        for (int c=0;c<64;c++){
            float4 a0 = *(const float4*)&h1T[c*136 + ty*8];
            float4 a1 = *(const float4*)&h1T[c*136 + ty*8 + 4];
            float4 w0 = *(const float4*)&w2s[c*128 + tx*8];
            float4 w1 = *(const float4*)&w2s[c*128 + tx*8 + 4];
            float av[8] = {a0.x,a0.y,a0.z,a0.w,a1.x,a1.y,a1.z,a1.w};
            float bb[8] = {w0.x,w0.y,w0.z,w0.w,w1.x,w1.y,w1.z,w1.w};
#pragma unroll
            for (int i=0;i<8;i++)
#pragma unroll
                for (int o=0;o<8;o++) acc[i][o] = fmaf(av[i], bb[o], acc[i][o]);
        }
#pragma unroll
        for (int o=0;o<8;o++){
            float bias = b2s[tx*8+o];
            float pm = -3.4e38f;
#pragma unroll
            for (int i=0;i<8;i++)
                pm = fmaxf(pm, leaky(acc[i][o] + bias));
            red[ty*128 + tx*8 + o] = pm;
        }
    }
    __syncthreads();

    for (int e=tid; e<1024; e+=256){
        int o = e & 127;
        int p = e >> 7;
        float v = fmaxf(red[(2*p)*128 + o], red[(2*p+1)*128 + o]);
        out[((long)(b*128 + o))*NP + n0 + p] = v;
    }
}

extern "C" void kernel_launch(void* const* d_in, const int* in_sizes, int n_in,
                              void* d_out, int out_size){
    const float* feat = (const float*)d_in[0];
    const float* pos  = (const float*)d_in[1];
    const float* Wn   = (const float*)d_in[2];
    const float* bn   = (const float*)d_in[3];
    const float* We   = (const float*)d_in[4];
    const float* be   = (const float*)d_in[5];
    const float* W1   = (const float*)d_in[6];
    const float* b1   = (const float*)d_in[7];
    const float* W2   = (const float*)d_in[8];
    const float* b2   = (const float*)d_in[9];
    float* out = (float*)d_out;

    cudaFuncSetAttribute(u_kernel,  cudaFuncAttributeMaxDynamicSharedMemorySize, 65536);
    cudaFuncSetAttribute(edge_main, cudaFuncAttributeMaxDynamicSharedMemorySize, 98304);

    prep_kernel<<<80,256>>>(Wn, We, W1, W2);
    knn_pass1<<<256,128>>>(pos);
    knn_pass2<<<256,256>>>(pos);
    knn_pass3<<<64,256>>>(pos);
    u_kernel<<<128,256,65536>>>(feat);
    edge_main<<<2048,256,96000>>>(bn, be, b1, b2, out);
}

// round 5
// speedup vs baseline: 2.2935x; 1.1544x over previous
#include <cuda_runtime.h>

#define NP 8192
#define NQ (2*NP)

__device__ __align__(16) float g_U[NQ*128];
__device__ float g_cmin[NQ*16];
__device__ unsigned long long g_surv[(long)NQ*8*64];
__device__ int   g_scnt[NQ*8];
__device__ int   g_knn[NQ*16];
__device__ __align__(16) float g_wu [64*128];
__device__ __align__(16) float g_w1t[64*64];
__device__ __align__(16) float g_w2t[64*128];

__device__ __forceinline__ float leaky(float v){ return fmaxf(v, 0.2f*v); }
__device__ __forceinline__ float distp(float xi,float yi,float zi,const float4 c){
    return fmaf(zi,c.z,fmaf(yi,c.y,fmaf(xi,c.x,c.w)));
}
__device__ __forceinline__ unsigned int okey(float d){
    unsigned int u = __float_as_uint(d);
    u ^= ((unsigned int)((int)u >> 31)) | 0x80000000u;
    return u;
}

// ---------------- prep: transpose weights once ----------------
__global__ void prep_kernel(const float* __restrict__ Wn, const float* __restrict__ We,
                            const float* __restrict__ W1, const float* __restrict__ W2){
    int i = blockIdx.x*blockDim.x + threadIdx.x;
    if (i < 8192){
        int c = i >> 7, o = i & 127;
        g_wu[i] = (o < 64) ? Wn[o*64 + c] : We[(o-64)*64 + c];
    } else if (i < 12288){
        int j = i - 8192; int c = j >> 6, o = j & 63;
        g_w1t[j] = W1[o*64 + c];
    } else if (i < 20480){
        int j = i - 12288; int c = j >> 7, o = j & 127;
        g_w2t[j] = W2[o*64 + c];
    }
}

// ---------- KNN pass 1: branchless chunk-mins. thread = (query, quarter of 2048) ----------
__global__ void knn_pass1(const float* __restrict__ pos){
    __shared__ float4 tile[256];
    int bx = blockIdx.x;              // 256 blocks x 256 threads
    int b  = bx >> 7;
    int r  = bx & 127;
    int quarter = r >> 5;             // [0,4)
    int n  = (r & 31)*256 + threadIdx.x;
    const float* pb = pos + b*NP*3;
    float xi = pb[n*3+0], yi = pb[n*3+1], zi = pb[n*3+2];
    long obase = ((long)(b*NP + n))*16 + quarter*4;

#pragma unroll
    for (int c4 = 0; c4 < 4; c4++){
        float mA = 3.4e38f, mB = 3.4e38f;
#pragma unroll
        for (int t2 = 0; t2 < 2; t2++){
            int jb = quarter*2048 + c4*512 + t2*256;
            int j  = jb + threadIdx.x;
            float x = pb[j*3+0], y = pb[j*3+1], z = pb[j*3+2];
            float sq = x*x; sq = fmaf(y,y,sq); sq = fmaf(z,z,sq);
            __syncthreads();
            tile[threadIdx.x] = make_float4(-2.0f*x, -2.0f*y, -2.0f*z, sq);
            __syncthreads();
#pragma unroll 8
            for (int jj = 0; jj < 256; jj += 4){
                float d0 = distp(xi,yi,zi, tile[jj+0]);
                float d1 = distp(xi,yi,zi, tile[jj+1]);
                float d2 = distp(xi,yi,zi, tile[jj+2]);
                float d3 = distp(xi,yi,zi, tile[jj+3]);
                mA = fminf(mA, fminf(d0,d1));
                mB = fminf(mB, fminf(d2,d3));
            }
        }
        g_cmin[obase + c4] = fminf(mA, mB);
    }
}

// ---------- KNN pass 2: filtered survivor scan, thread = (query, seg of 1024) ----------
__global__ void knn_pass2(const float* __restrict__ pos){
    __shared__ float4 tile[256];
    int bx  = blockIdx.x;             // 512 blocks x 256 threads
    int seg = bx & 7;
    int q   = (bx >> 3)*256 + threadIdx.x;
    int b   = q >> 13;
    int n   = q & 8191;
    const float* pb = pos + b*NP*3;
    float xi = pb[n*3+0], yi = pb[n*3+1], zi = pb[n*3+2];

    float T0 = -3.4e38f;
#pragma unroll
    for (int s = 0; s < 16; s++) T0 = fmaxf(T0, g_cmin[(long)q*16 + s]);

    unsigned long long* sv = &g_surv[((long)q*8 + seg)*64];
    int c = 0;
#pragma unroll
    for (int t = 0; t < 4; t++){
        int jb = seg*1024 + t*256;
        int j  = jb + threadIdx.x;
        float x = pb[j*3+0], y = pb[j*3+1], z = pb[j*3+2];
        float sq = x*x; sq = fmaf(y,y,sq); sq = fmaf(z,z,sq);
        __syncthreads();
        tile[threadIdx.x] = make_float4(-2.0f*x, -2.0f*y, -2.0f*z, sq);
        __syncthreads();
        for (int jj = 0; jj < 256; jj += 4){
            float d0 = distp(xi,yi,zi, tile[jj+0]);
            float d1 = distp(xi,yi,zi, tile[jj+1]);
            float d2 = distp(xi,yi,zi, tile[jj+2]);
            float d3 = distp(xi,yi,zi, tile[jj+3]);
            float mn = fminf(fminf(d0,d1), fminf(d2,d3));
            if (mn <= T0){
                float dd[4] = {d0,d1,d2,d3};
#pragma unroll
                for (int u = 0; u < 4; u++){
                    if (dd[u] <= T0 && c < 64){
                        sv[c] = ((unsigned long long)okey(dd[u]) << 32) | (unsigned int)(jb + jj + u);
                        c++;
                    }
                }
            }
        }
    }
    g_scnt[(long)q*8 + seg] = c;
}

// ---------- KNN pass 3: warp per query, smem survivor buffer, 16x warp-min ----------
__global__ void knn_pass3(const float* __restrict__ pos){
    __shared__ unsigned long long wbuf[8][512];
    int w    = threadIdx.x >> 5;
    int lane = threadIdx.x & 31;
    int q    = blockIdx.x*8 + w;       // 2048 blocks x 8 warps

    int cs = (lane < 8) ? g_scnt[(long)q*8 + lane] : 0;
    unsigned ovfm = __ballot_sync(0xffffffff, lane < 8 && cs >= 64);
    int pre = cs;
#pragma unroll
    for (int o = 1; o < 8; o <<= 1){
        int v = __shfl_up_sync(0xffffffff, pre, o);
        if (lane >= o) pre += v;
    }
    int ip[8];
#pragma unroll
    for (int s = 0; s < 8; s++) ip[s] = __shfl_sync(0xffffffff, pre, s);
    int ctot = ip[7];

    if (!ovfm){
        for (int t = lane; t < ctot; t += 32){
            int s = 0, base = 0;
#pragma unroll
            for (int k = 0; k < 7; k++){
                if (t >= ip[k]){ s = k+1; base = ip[k]; }
            }
            wbuf[w][t] = g_surv[((long)q*8 + s)*64 + (t - base)];
        }
        __syncwarp();
        for (int r = 0; r < 16; r++){
            unsigned long long mk = ~0ull; int mp = 0;
            for (int t = lane; t < ctot; t += 32){
                unsigned long long k = wbuf[w][t];
                if (k < mk){ mk = k; mp = t; }
            }
#pragma unroll
            for (int o = 16; o; o >>= 1){
                unsigned long long ok = __shfl_down_sync(0xffffffff, mk, o);
                int op = __shfl_down_sync(0xffffffff, mp, o);
                if (ok < mk){ mk = ok; mp = op; }
            }
            mp = __shfl_sync(0xffffffff, mp, 0);
            if (lane == 0){
                g_knn[(long)q*16 + r] = (int)(mk & 0xffffffffull);
                wbuf[w][mp] = ~0ull;
            }
            __syncwarp();
        }
    } else if (lane == 0){
        // exact full rescan fallback (statistically never taken)
        int b = q >> 13, n = q & 8191;
        const float* pb = pos + b*NP*3;
        float xi = pb[n*3+0], yi = pb[n*3+1], zi = pb[n*3+2];
        unsigned long long bk[16];
#pragma unroll
        for (int s = 0; s < 16; s++) bk[s] = ~0ull;
        unsigned long long worst = ~0ull; int ws = 0;
        for (int j = 0; j < NP; j++){
            float x = pb[j*3+0], y = pb[j*3+1], z = pb[j*3+2];
            float sq = x*x; sq = fmaf(y,y,sq); sq = fmaf(z,z,sq);
            float d = fmaf(zi,-2.0f*z, fmaf(yi,-2.0f*y, fmaf(xi,-2.0f*x, sq)));
            unsigned long long key = ((unsigned long long)okey(d) << 32) | (unsigned int)j;
            if (key < worst){
                bk[ws] = key;
                worst = bk[0]; ws = 0;
                for (int s = 1; s < 16; s++) if (bk[s] > worst){ worst = bk[s]; ws = s; }
            }
        }
        for (int rr = 0; rr < 16; rr++){
            unsigned long long best = ~0ull; int bj = 0;
            for (int s = 0; s < 16; s++) if (bk[s] < best){ best = bk[s]; bj = s; }
            bk[bj] = ~0ull;
            g_knn[(long)q*16 + rr] = (int)(best & 0xffffffffull);
        }
    }
}

// ---------------- U = [W_node; W_edge] * feat ----------------
__global__ void u_kernel(const float* __restrict__ feat){
    extern __shared__ float smC[];
    float* fs = smC;
    float* ws = smC + 64*128;
    int q0 = blockIdx.x*128;
    int b  = q0 >> 13;
    int n0 = q0 & 8191;
    for (int i=threadIdx.x; i<64*128; i+=256){
        int c = i>>7, nn = i&127;
        fs[i] = feat[((long)(b*64 + c))*NP + n0 + nn];
        ws[i] = g_wu[i];
    }
    __syncthreads();
    int tx = threadIdx.x & 15, ty = threadIdx.x >> 4;
    float acc[8][8];
#pragma unroll
    for (int i=0;i<8;i++)
#pragma unroll
        for (int j=0;j<8;j++) acc[i][j]=0.f;
#pragma unroll 4
    for (int c=0;c<64;c++){
        float4 a0 = *(const float4*)&fs[c*128 + ty*8];
        float4 a1 = *(const float4*)&fs[c*128 + ty*8 + 4];
        float4 w0 = *(const float4*)&ws[c*128 + tx*8];
        float4 w1 = *(const float4*)&ws[c*128 + tx*8 + 4];
        float av[8] = {a0.x,a0.y,a0.z,a0.w,a1.x,a1.y,a1.z,a1.w};
        float bv[8] = {w0.x,w0.y,w0.z,w0.w,w1.x,w1.y,w1.z,w1.w};
#pragma unroll
        for (int i=0;i<8;i++)
#pragma unroll
            for (int j=0;j<8;j++) acc[i][j] = fmaf(av[i], bv[j], acc[i][j]);
    }
#pragma unroll
    for (int i=0;i<8;i++){
        long q = q0 + ty*8 + i;
        float* r = &g_U[q*128 + tx*8];
        *(float4*)r     = make_float4(acc[i][0],acc[i][1],acc[i][2],acc[i][3]);
        *(float4*)(r+4) = make_float4(acc[i][4],acc[i][5],acc[i][6],acc[i][7]);
    }
}

// ---------------- fused gather + h1 + m1 + m2 + maxpool ----------------
__global__ void edge_main(const float* __restrict__ bn,  const float* __restrict__ be,
                          const float* __restrict__ vb1, const float* __restrict__ vb2,
                          float* __restrict__ out){
    extern __shared__ float sm[];
    float* h1T = sm;                  // [64][136], reused as h2T
    float* w1s = h1T + 64*136;
    float* w2s = w1s + 64*64;
    float* uec = w2s + 64*128;
    float* red = uec + 512;
    float* bns = red + 2048;
    float* bes = bns + 64;
    float* b1s = bes + 64;
    float* b2s = b1s + 64;
    int*   idxs = (int*)(b2s + 128);

    int q0 = blockIdx.x*8;
    int b  = q0 >> 13;
    int n0 = q0 & 8191;
    int tid = threadIdx.x;

    for (int i=tid;i<4096;i+=256) w1s[i] = g_w1t[i];
    for (int i=tid;i<8192;i+=256) w2s[i] = g_w2t[i];
    if (tid<64){ bns[tid]=bn[tid]; bes[tid]=be[tid]; b1s[tid]=vb1[tid]; }
    if (tid<128) b2s[tid]=vb2[tid];
    if (tid<128) idxs[tid] = g_knn[(long)q0*16 + tid];
    for (int i=tid;i<512;i+=256){ int p=i>>6, j=i&63; uec[i] = g_U[(long)(q0+p)*128 + 64 + j]; }
    __syncthreads();

    { // stage A
        int m  = tid >> 1;
        int jb = (tid & 1) * 32;
        int p  = m >> 4;
        int nb = idxs[m];
        const float* Ur = &g_U[(long)((b<<13) + nb)*128];
#pragma unroll
        for (int v=0; v<8; v++){
            float4 un = *(const float4*)&Ur[jb + v*4];
            float4 ue = *(const float4*)&Ur[64 + jb + v*4];
            float unv[4] = {un.x,un.y,un.z,un.w};
            float uev[4] = {ue.x,ue.y,ue.z,ue.w};
#pragma unroll
            for (int e=0;e<4;e++){
                int j = jb + v*4 + e;
                float a = leaky(unv[e] + bns[j]);
                float c = leaky(uev[e] - uec[p*64 + j] + bes[j]);
                h1T[j*136 + m] = a + c;
            }
        }
    }
    __syncthreads();

    int tx = tid & 15, ty = tid >> 4;

    { // stage B
        float acc[8][4];
#pragma unroll
        for (int i=0;i<8;i++)
#pragma unroll
            for (int o=0;o<4;o++) acc[i][o]=0.f;
#pragma unroll 4
        for (int c=0;c<64;c++){
            float4 a0 = *(const float4*)&h1T[c*136 + ty*8];
            float4 a1 = *(const float4*)&h1T[c*136 + ty*8 + 4];
            float4 wv = *(const float4*)&w1s[c*64 + tx*4];
            float av[8] = {a0.x,a0.y,a0.z,a0.w,a1.x,a1.y,a1.z,a1.w};
            float bb[4] = {wv.x,wv.y,wv.z,wv.w};
#pragma unroll
            for (int i=0;i<8;i++)
#pragma unroll
                for (int o=0;o<4;o++) acc[i][o] = fmaf(av[i], bb[o], acc[i][o]);
        }
        __syncthreads();
#pragma unroll
        for (int i=0;i<8;i++){
            int m = ty*8 + i;
#pragma unroll
            for (int o=0;o<4;o++)
                h1T[(tx*4+o)*136 + m] = leaky(acc[i][o] + b1s[tx*4+o]);
        }
    }
    __syncthreads();

    { // stage C
        float acc[8][8];
#pragma unroll
        for (int i=0;i<8;i++)
#pragma unroll
            for (int o=0;o<8;o++) acc[i][o]=0.f;
#pragma unroll 4
        for (int c=0;c<64;c++){
            float4 a0 = *(const float4*)&h1T[c*136 + ty*8];
            float4 a1 = *(const float4*)&h1T[c*136 + ty*8 + 4];
            float4 w0 = *(const float4*)&w2s[c*128 + tx*8];
            float4 w1 = *(const float4*)&w2s[c*128 + tx*8 + 4];
            float av[8] = {a0.x,a0.y,a0.z,a0.w,a1.x,a1.y,a1.z,a1.w};
            float bb[8] = {w0.x,w0.y,w0.z,w0.w,w1.x,w1.y,w1.z,w1.w};
#pragma unroll
            for (int i=0;i<8;i++)
#pragma unroll
                for (int o=0;o<8;o++) acc[i][o] = fmaf(av[i], bb[o], acc[i][o]);
        }
#pragma unroll
        for (int o=0;o<8;o++){
            float bias = b2s[tx*8+o];
            float pm = -3.4e38f;
#pragma unroll
            for (int i=0;i<8;i++)
                pm = fmaxf(pm, leaky(acc[i][o] + bias));
            red[ty*128 + tx*8 + o] = pm;
        }
    }
    __syncthreads();

    for (int e=tid; e<1024; e+=256){
        int o = e & 127;
        int p = e >> 7;
        float v = fmaxf(red[(2*p)*128 + o], red[(2*p+1)*128 + o]);
        out[((long)(b*128 + o))*NP + n0 + p] = v;
    }
}

extern "C" void kernel_launch(void* const* d_in, const int* in_sizes, int n_in,
                              void* d_out, int out_size){
    const float* feat = (const float*)d_in[0];
    const float* pos  = (const float*)d_in[1];
    const float* Wn   = (const float*)d_in[2];
    const float* bn   = (const float*)d_in[3];
    const float* We   = (const float*)d_in[4];
    const float* be   = (const float*)d_in[5];
    const float* W1   = (const float*)d_in[6];
    const float* b1   = (const float*)d_in[7];
    const float* W2   = (const float*)d_in[8];
    const float* b2   = (const float*)d_in[9];
    float* out = (float*)d_out;

    cudaFuncSetAttribute(u_kernel,  cudaFuncAttributeMaxDynamicSharedMemorySize, 65536);
    cudaFuncSetAttribute(edge_main, cudaFuncAttributeMaxDynamicSharedMemorySize, 98304);

    prep_kernel<<<80,256>>>(Wn, We, W1, W2);
    knn_pass1<<<256,256>>>(pos);
    knn_pass2<<<512,256>>>(pos);
    knn_pass3<<<2048,256>>>(pos);
    u_kernel<<<128,256,65536>>>(feat);
    edge_main<<<2048,256,96000>>>(bn, be, b1, b2, out);
}